// round 15
// baseline (speedup 1.0000x reference)
#include <cuda_runtime.h>

// VolumeRenderer: B=4, HW=65536, N=48
// inputs: rgb (B,HW,N,3) f32, sigma (B,HW,N,1) f32, z_vals (B,HW,N) f32
// output: rgb_map (B*HW,3) then depth_map (B*HW), concatenated f32.
//
// Packed mapping: lane j (j<12 of a 16-lane group) owns samples 4j..4j+3
// of one ray; warp = 2 rays per pair, 2 pairs per warp front-batched.
// This round: all global traffic uses streaming cache policy (__ldcs /
// __stcs, evict-first) -- data is stream-once, so don't pay L1/L2
// allocation-priority overhead for it.

#define TOTAL_RAYS (4 * 65536)   // 262144
#define NSAMP      48
#define RAYS_PB    32            // 256 threads = 8 warps x 2 pairs x 2 rays

#define FULLM 0xffffffffu

struct RayPack { float4 z4, s4, ra, rb, rc; };

__device__ __forceinline__ RayPack load_pack(
    const float* __restrict__ rgb, const float* __restrict__ sigma,
    const float* __restrict__ z_vals, int ray, int sub, bool act)
{
    RayPack v;
    v.z4 = make_float4(0.f, 0.f, 0.f, 0.f);
    v.s4 = v.ra = v.rb = v.rc = v.z4;
    if (act) {
        const size_t zb = (size_t)ray * NSAMP;
        const size_t rbase = (size_t)ray * (NSAMP * 3);
        v.z4 = __ldcs(reinterpret_cast<const float4*>(z_vals + zb + 4 * sub));
        v.s4 = __ldcs(reinterpret_cast<const float4*>(sigma  + zb + 4 * sub));
        // elements 12j..12j+11: ra=(r0,g0,b0,r1) rb=(g1,b1,r2,g2) rc=(b2,r3,g3,b3)
        v.ra = __ldcs(reinterpret_cast<const float4*>(rgb + rbase + 12 * sub + 0));
        v.rb = __ldcs(reinterpret_cast<const float4*>(rgb + rbase + 12 * sub + 4));
        v.rc = __ldcs(reinterpret_cast<const float4*>(rgb + rbase + 12 * sub + 8));
    }
    return v;
}

__device__ __forceinline__ void compute_pair(
    const RayPack& v, int ray, int sub, bool act, float* __restrict__ out)
{
    // distances: d_i = z_{i+1} - z_i ; sample 47 capped at 1e10
    float zn = __shfl_down_sync(FULLM, v.z4.x, 1, 16);   // z[4j+4]
    float d0 = v.z4.y - v.z4.x;
    float d1 = v.z4.z - v.z4.y;
    float d2 = v.z4.w - v.z4.z;
    float d3 = (sub == 11) ? 1e10f : (zn - v.z4.w);

    // opacities
    float e0 = __expf(-v.s4.x * d0);
    float e1 = __expf(-v.s4.y * d1);
    float e2 = __expf(-v.s4.z * d2);
    float e3 = __expf(-v.s4.w * d3);
    float t0 = e0 + 1e-10f, t1 = e1 + 1e-10f;
    float t2 = e2 + 1e-10f, t3 = e3 + 1e-10f;

    // in-lane prefix products
    float q1 = t0;
    float q2 = t0 * t1;
    float q3 = q2 * t2;
    float P  = act ? (q3 * t3) : 1.0f;   // idle lanes neutral

    // width-16 inclusive scan of lane products (4 SHFL)
    float incl = P;
#pragma unroll
    for (int k = 1; k < 16; k <<= 1) {
        float u = __shfl_up_sync(FULLM, incl, k, 16);
        if (sub >= k) incl *= u;
    }
    float ex = __shfl_up_sync(FULLM, incl, 1, 16);
    float Tl = (sub == 0) ? 1.0f : ex;

    // weights
    float w0 = Tl * (1.0f - e0);
    float w1 = Tl * q1 * (1.0f - e1);
    float w2 = Tl * q2 * (1.0f - e2);
    float w3 = Tl * q3 * (1.0f - e3);

    // accumulate (channel pattern compile-time)
    float R = fmaf(w0, v.ra.x, fmaf(w1, v.ra.w, fmaf(w2, v.rb.z, w3 * v.rc.y)));
    float G = fmaf(w0, v.ra.y, fmaf(w1, v.rb.x, fmaf(w2, v.rb.w, w3 * v.rc.z)));
    float B = fmaf(w0, v.ra.z, fmaf(w1, v.rb.y, fmaf(w2, v.rc.x, w3 * v.rc.w)));
    float D = fmaf(w0, v.z4.x, fmaf(w1, v.z4.y, fmaf(w2, v.z4.z, w3 * v.z4.w)));
    if (!act) { R = 0.f; G = 0.f; B = 0.f; D = 0.f; }

    // transpose-reduce across the 16-lane group (10 SHFL)
#pragma unroll
    for (int k = 1; k <= 2; k <<= 1) {
        R += __shfl_xor_sync(FULLM, R, k, 16);
        G += __shfl_xor_sync(FULLM, G, k, 16);
        B += __shfl_xor_sync(FULLM, B, k, 16);
        D += __shfl_xor_sync(FULLM, D, k, 16);
    }
    int c = sub & 3;
    float vs = (c == 0) ? R : (c == 1) ? G : (c == 2) ? B : D;
    vs += __shfl_xor_sync(FULLM, vs, 4, 16);
    vs += __shfl_xor_sync(FULLM, vs, 8, 16);

    if (sub < 3) {
        __stcs(out + (size_t)ray * 3 + sub, vs);
    } else if (sub == 3) {
        __stcs(out + (size_t)TOTAL_RAYS * 3 + ray, vs);
    }
}

__global__ __launch_bounds__(256, 4)
void volrend_kernel(const float* __restrict__ rgb,
                    const float* __restrict__ sigma,
                    const float* __restrict__ z_vals,
                    float* __restrict__ out)
{
    const int tid  = threadIdx.x;
    const int warp = tid >> 5;
    const int lane = tid & 31;
    const int sub  = lane & 15;
    const int half = lane >> 4;
    const bool act = (sub < 12);

    const int base = blockIdx.x * RAYS_PB + warp * 4;
    const int rayA = base + half;
    const int rayB = base + 2 + half;

    // front-batch BOTH pairs' loads: one DRAM wait covers 2 compute phases
    RayPack va = load_pack(rgb, sigma, z_vals, rayA, sub, act);
    RayPack vb = load_pack(rgb, sigma, z_vals, rayB, sub, act);

    compute_pair(va, rayA, sub, act, out);
    compute_pair(vb, rayB, sub, act, out);
}

extern "C" void kernel_launch(void* const* d_in, const int* in_sizes, int n_in,
                              void* d_out, int out_size)
{
    const float* rgb    = (const float*)d_in[0];
    const float* sigma  = (const float*)d_in[1];
    const float* z_vals = (const float*)d_in[2];
    float* out = (float*)d_out;

    dim3 grid(TOTAL_RAYS / RAYS_PB);   // 8192 blocks
    dim3 block(256);
    volrend_kernel<<<grid, block>>>(rgb, sigma, z_vals, out);
}

// round 16
// speedup vs baseline: 1.0564x; 1.0564x over previous
#include <cuda_runtime.h>

// VolumeRenderer: B=4, HW=65536, N=48
// inputs: rgb (B,HW,N,3) f32, sigma (B,HW,N,1) f32, z_vals (B,HW,N) f32
// output: rgb_map (B*HW,3) then depth_map (B*HW), concatenated f32.
//
// Final composition: R13's single-pair, high-occupancy structure (lane j
// of each 16-lane group owns samples 4j..4j+3; warp = 2 rays; all float4
// loads; in-register prefix + one width-16 shuffle scan) combined with
// R15's streaming cache policy (__ldcs/__stcs) for the stream-once data.

#define TOTAL_RAYS (4 * 65536)   // 262144
#define NSAMP      48
#define RAYS_PB    16            // 256 threads = 8 warps x 2 rays

#define FULLM 0xffffffffu

__global__ __launch_bounds__(256)
void volrend_kernel(const float* __restrict__ rgb,
                    const float* __restrict__ sigma,
                    const float* __restrict__ z_vals,
                    float* __restrict__ out)
{
    const int tid  = threadIdx.x;
    const int warp = tid >> 5;
    const int lane = tid & 31;
    const int sub  = lane & 15;          // lane within 16-lane ray group
    const int half = lane >> 4;          // which ray of the pair

    const int ray  = blockIdx.x * RAYS_PB + warp * 2 + half;
    const bool act = (sub < 12);         // 12 owner lanes x 4 samples = 48

    const size_t zb = (size_t)ray * NSAMP;
    const size_t rb = (size_t)ray * (NSAMP * 3);

    // ---- float4 streaming loads ----
    float4 z4 = make_float4(0.f, 0.f, 0.f, 0.f);
    float4 s4 = z4, ra = z4, rbv = z4, rc = z4;
    if (act) {
        z4  = __ldcs(reinterpret_cast<const float4*>(z_vals + zb + 4 * sub));
        s4  = __ldcs(reinterpret_cast<const float4*>(sigma  + zb + 4 * sub));
        // elements 12j..12j+11: ra=(r0,g0,b0,r1) rbv=(g1,b1,r2,g2) rc=(b2,r3,g3,b3)
        ra  = __ldcs(reinterpret_cast<const float4*>(rgb + rb + 12 * sub + 0));
        rbv = __ldcs(reinterpret_cast<const float4*>(rgb + rb + 12 * sub + 4));
        rc  = __ldcs(reinterpret_cast<const float4*>(rgb + rb + 12 * sub + 8));
    }

    // ---- distances: d_i = z_{i+1} - z_i ; sample 47 capped at 1e10 ----
    float zn = __shfl_down_sync(FULLM, z4.x, 1, 16);   // z[4j+4]
    float d0 = z4.y - z4.x;
    float d1 = z4.z - z4.y;
    float d2 = z4.w - z4.z;
    float d3 = (sub == 11) ? 1e10f : (zn - z4.w);

    // ---- opacities ----
    float e0 = __expf(-s4.x * d0);
    float e1 = __expf(-s4.y * d1);
    float e2 = __expf(-s4.z * d2);
    float e3 = __expf(-s4.w * d3);
    float t0 = e0 + 1e-10f, t1 = e1 + 1e-10f;
    float t2 = e2 + 1e-10f, t3 = e3 + 1e-10f;

    // ---- in-lane prefix products ----
    float q1 = t0;
    float q2 = t0 * t1;
    float q3 = q2 * t2;
    float P  = act ? (q3 * t3) : 1.0f;   // idle lanes neutral

    // ---- width-16 inclusive scan of lane products (4 SHFL) ----
    float incl = P;
#pragma unroll
    for (int k = 1; k < 16; k <<= 1) {
        float u = __shfl_up_sync(FULLM, incl, k, 16);
        if (sub >= k) incl *= u;
    }
    float ex = __shfl_up_sync(FULLM, incl, 1, 16);
    float Tl = (sub == 0) ? 1.0f : ex;   // product of all earlier lanes

    // ---- weights ----
    float w0 = Tl * (1.0f - e0);
    float w1 = Tl * q1 * (1.0f - e1);
    float w2 = Tl * q2 * (1.0f - e2);
    float w3 = Tl * q3 * (1.0f - e3);

    // ---- accumulate (channel pattern compile-time) ----
    float R = fmaf(w0, ra.x, fmaf(w1, ra.w, fmaf(w2, rbv.z, w3 * rc.y)));
    float G = fmaf(w0, ra.y, fmaf(w1, rbv.x, fmaf(w2, rbv.w, w3 * rc.z)));
    float B = fmaf(w0, ra.z, fmaf(w1, rbv.y, fmaf(w2, rc.x,  w3 * rc.w)));
    float D = fmaf(w0, z4.x, fmaf(w1, z4.y, fmaf(w2, z4.z,  w3 * z4.w)));
    if (!act) { R = 0.f; G = 0.f; B = 0.f; D = 0.f; }

    // ---- transpose-reduce across the 16-lane group (10 SHFL) ----
#pragma unroll
    for (int k = 1; k <= 2; k <<= 1) {
        R += __shfl_xor_sync(FULLM, R, k, 16);
        G += __shfl_xor_sync(FULLM, G, k, 16);
        B += __shfl_xor_sync(FULLM, B, k, 16);
        D += __shfl_xor_sync(FULLM, D, k, 16);
    }
    int c = sub & 3;
    float vs = (c == 0) ? R : (c == 1) ? G : (c == 2) ? B : D;
    vs += __shfl_xor_sync(FULLM, vs, 4, 16);
    vs += __shfl_xor_sync(FULLM, vs, 8, 16);

    if (sub < 3) {
        __stcs(out + (size_t)ray * 3 + sub, vs);
    } else if (sub == 3) {
        __stcs(out + (size_t)TOTAL_RAYS * 3 + ray, vs);
    }
}

extern "C" void kernel_launch(void* const* d_in, const int* in_sizes, int n_in,
                              void* d_out, int out_size)
{
    const float* rgb    = (const float*)d_in[0];
    const float* sigma  = (const float*)d_in[1];
    const float* z_vals = (const float*)d_in[2];
    float* out = (float*)d_out;

    dim3 grid(TOTAL_RAYS / RAYS_PB);   // 16384 blocks
    dim3 block(256);
    volrend_kernel<<<grid, block>>>(rgb, sigma, z_vals, out);
}